// round 15
// baseline (speedup 1.0000x reference)
#include <cuda_runtime.h>
#include <cstdint>
#include <math.h>

#define E_EXPERTS 5
#define CDIM      256
#define HALF      128
#define QUART     64
#define BDIM      8
#define NPIX      6400
#define PIX       64

typedef uint32_t u32;
typedef uint16_t u16;

__device__ float g_pooled[BDIM * CDIM];

// ---------- fp16 helpers ----------
__device__ __forceinline__ u32 pack_f16x2(float lo, float hi) {
    u32 r; asm("cvt.rn.f16x2.f32 %0, %1, %2;" : "=r"(r) : "f"(hi), "f"(lo)); return r;
}

// ---------- warp mma: D(16x8,f32) += A(16x16,f16 row) * B(16x8,f16 col) ----------
__device__ __forceinline__ void mma_f16(float* d, const u32* a, const u32* b) {
    asm volatile("mma.sync.aligned.m16n8k16.row.col.f32.f16.f16.f32 "
        "{%0,%1,%2,%3},{%4,%5,%6,%7},{%8,%9},{%0,%1,%2,%3};"
        : "+f"(d[0]), "+f"(d[1]), "+f"(d[2]), "+f"(d[3])
        : "r"(a[0]), "r"(a[1]), "r"(a[2]), "r"(a[3]), "r"(b[0]), "r"(b[1]));
}

// ---------- ldmatrix x4 transposed (b16) ----------
__device__ __forceinline__ void ldsm_x4_trans(u32* r, u32 saddr) {
    asm volatile("ldmatrix.sync.aligned.m8n8.x4.trans.shared.b16 {%0,%1,%2,%3}, [%4];"
        : "=r"(r[0]), "=r"(r[1]), "=r"(r[2]), "=r"(r[3]) : "r"(saddr));
}

// ======================= gate kernel 1 (pool) =======================
__global__ void __launch_bounds__(320) gate_pool(const float* __restrict__ x) {
    int bc = blockIdx.x;
    const float4* p4 = (const float4*)(x + (size_t)bc * NPIX);
    float s = 0.f;
    #pragma unroll
    for (int k = 0; k < 5; k++) {
        float4 v = __ldg(p4 + k * 320 + threadIdx.x);
        s += (v.x + v.y) + (v.z + v.w);
    }
    __shared__ float red[10];
    #pragma unroll
    for (int o = 16; o; o >>= 1) s += __shfl_down_sync(0xffffffffu, s, o);
    if ((threadIdx.x & 31) == 0) red[threadIdx.x >> 5] = s;
    __syncthreads();
    if (threadIdx.x < 32) {
        float v = (threadIdx.x < 10) ? red[threadIdx.x] : 0.f;
        #pragma unroll
        for (int o = 8; o; o >>= 1) v += __shfl_down_sync(0xffffffffu, v, o);
        if (threadIdx.x == 0) g_pooled[bc] = v * (1.0f / (float)NPIX);
    }
}

// ======================= smem layout (identical to round 14) =======================
#define W_OFF    36864
#define W1_OFF   110592
#define SA_OFF   129024
#define SS_OFF   129536
#define SMEM_BYTES 130048

__global__ void __launch_bounds__(1024, 1) moe_expert(
    const float* __restrict__ x,
    const float* __restrict__ Wg,   const float* __restrict__ bg,
    const float* __restrict__ Wrgb, const float* __restrict__ brgb,
    const float* __restrict__ Wtir, const float* __restrict__ btir,
    const float* __restrict__ Wt1,  const float* __restrict__ bt1,
    const float* __restrict__ Wt2,  const float* __restrict__ bt2,
    float* __restrict__ out)
{
    extern __shared__ char smc[];
    float* sA = (float*)(smc + SA_OFF);
    float* sS = (float*)(smc + SS_OFF);

    const int t    = threadIdx.x;
    const int w    = t >> 5;
    const int lane = t & 31;
    const int gr   = lane >> 2;
    const int q    = lane & 3;
    const int br   = w >> 4;            // 0=RGB (warps 0-15), 1=TIR (16-31)
    const int wsub = w & 15;
    // GEMM1 warp tile: m16 x px32
    const int mt   = wsub >> 1;         // m-tile 0..7 -> rows mt*16
    const int phf  = wsub & 1;          // px half 0..1 -> px phf*32
    const int rbase = mt * 16;
    // GEMM2 warp tile: px16 x m16
    const int pxt  = wsub >> 2;         // px 16-tile 0..3
    const int mj   = wsub & 3;          // m 16-tile 0..3

    const int b = blockIdx.y;

    // ---- inline gate ----
    if (w < E_EXPERTS) {
        const float* pw = Wg + w * CDIM;
        const float* pp = g_pooled + b * CDIM;
        float s = 0.f;
        #pragma unroll
        for (int c = lane; c < CDIM; c += 32) s += pp[c] * pw[c];
        #pragma unroll
        for (int o = 16; o; o >>= 1) s += __shfl_down_sync(0xffffffffu, s, o);
        if (lane == 0) sS[w] = s + __ldg(bg + w);
    }
    __syncthreads();
    int e = 0;
    {
        float best = sS[0];
        #pragma unroll
        for (int i = 1; i < E_EXPERTS; i++) {
            float v = sS[i];
            if (v > best) { best = v; e = i; }
        }
    }

    // 18 blocks/batch: 10x6 + 8x5 = 100 tiles of 64 px
    const int ib    = blockIdx.x;
    const int tile0 = ib < 10 ? ib * 6 : 60 + (ib - 10) * 5;
    const int tcnt  = ib < 10 ? 6 : 5;

    // ---- per-thread constants ----
    const float bz0 = __ldg((br ? btir : brgb) + e * HALF + rbase + gr);
    const float bz1 = __ldg((br ? btir : brgb) + e * HALF + rbase + gr + 8);
    float w2x[2], w2y[2], b1x[2], b1y[2];
    #pragma unroll
    for (int j = 0; j < 2; j++) {
        int m0 = mj * 16 + j * 8 + 2 * q;
        w2x[j] = __ldg(Wt2 + e * QUART + m0);
        w2y[j] = __ldg(Wt2 + e * QUART + m0 + 1);
        b1x[j] = __ldg(bt1 + e * QUART + m0);
        b1y[j] = __ldg(bt1 + e * QUART + m0 + 1);
    }
    const float bt2v = __ldg(bt2 + e);

    // ------------ prologue: W' = W + I, W1 -> fp16 in smem ------------
    #pragma unroll
    for (int br2 = 0; br2 < 2; br2++) {
        const float* gW = (br2 ? Wtir : Wrgb) + (size_t)e * HALF * HALF;
        char* bh = smc + W_OFF + br2 * 36864;
        #pragma unroll 4
        for (int it = 0; it < 8; it++) {
            int lin = it * 1024 + t;           // 8192 = 128 o x 64 c-pairs
            int o = lin >> 6, c0 = (lin & 63) * 2;
            float2 v = __ldg((const float2*)(gW + o * 128 + c0));
            float vx = v.x + ((o == c0)     ? 1.f : 0.f);
            float vy = v.y + ((o == c0 + 1) ? 1.f : 0.f);
            int addr = (c0 >> 6) * 18432 + o * 144 + (c0 & 63) * 2;
            *(u32*)(bh + addr) = pack_f16x2(vx, vy);
        }
    }
    {
        const float* g1 = Wt1 + (size_t)e * QUART * HALF;
        char* bh = smc + W1_OFF;
        #pragma unroll 4
        for (int it = 0; it < 4; it++) {
            int lin = it * 1024 + t;           // 4096 = 64 m x 64 c-pairs
            int m = lin >> 6, c0 = (lin & 63) * 2;
            float2 v = __ldg((const float2*)(g1 + m * 128 + c0));
            int addr = (c0 >> 6) * 9216 + m * 144 + (c0 & 63) * 2;
            *(u32*)(bh + addr) = pack_f16x2(v.x, v.y);
        }
    }

    // ---- Bx builder mapping: cp8 = t>>3 (128 pairs), sub = t&7 ----
    const int cp8 = t >> 3;
    const int sub = t & 7;
    const int c0b = 2 * cp8;
    char* const bldr = smc + (c0b >> 7) * 18432 + ((c0b & 64) ? 9216 : 0);
    const int cin = (c0b & 63) * 2;
    const float* gx0 = x + ((size_t)(b * CDIM + c0b)) * NPIX;

    // ---- GEMM2 A ldmatrix lane base (transposed Dhi) ----
    const int l2   = lane & 7;
    const int tl   = lane >> 3;
    const int arow = l2 + ((tl & 2) ? 8 : 0);
    const int acol = pxt * 32 + ((tl & 1) ? 16 : 0);
    const u32 dsm_base = (u32)__cvta_generic_to_shared(smc + br * 18432)
                       + (u32)(arow * 144 + acol);

    for (int tt = 0; tt < tcnt; tt++) {
        const int pix0 = (tile0 + tt) * PIX;
        __syncthreads();   // region A free (covers prologue + gate on tt=0)

        // ---- build xhi fp16 tile (coalesced LDG + swizzled STS) ----
        {
            const float* g0 = gx0 + pix0;
            #pragma unroll
            for (int j = 0; j < 2; j++) {
                float4 a0 = __ldg((const float4*)(g0 + sub * 4 + j * 32));
                float4 a1 = __ldg((const float4*)(g0 + NPIX + sub * 4 + j * 32));
                int px0 = sub * 4 + j * 32;
                int cinx = cin ^ ((((px0 >> 3) & 7) << 4));
                *(u32*)(bldr + (px0    ) * 144 + cinx) = pack_f16x2(a0.x, a1.x);
                *(u32*)(bldr + (px0 + 1) * 144 + cinx) = pack_f16x2(a0.y, a1.y);
                *(u32*)(bldr + (px0 + 2) * 144 + cinx) = pack_f16x2(a0.z, a1.z);
                *(u32*)(bldr + (px0 + 3) * 144 + cinx) = pack_f16x2(a0.w, a1.w);
            }
        }
        __syncthreads();

        // ---- GEMM1: acc[4][4] = W'hi@xhi, warp tile m16 x px32 ----
        float acc[4][4];
        #pragma unroll
        for (int nt = 0; nt < 4; nt++)
            #pragma unroll
            for (int i = 0; i < 4; i++) acc[nt][i] = 0.f;
        {
            const char* Ah = smc + W_OFF + br * 36864;
            const char* Bh = smc + br * 18432;
            const int rb = (rbase + gr) * 144, rb8 = rb + 1152;
            #pragma unroll 2
            for (int kt = 0; kt < 8; kt++) {
                const int wp = (kt >> 2) * 18432 + (kt & 3) * 32 + q * 4;
                const int bplane = (kt >> 2) * 9216;
                const int bbyte  = (kt & 3) * 32 + q * 4;
                u32 ah[4];
                ah[0] = *(const u32*)(Ah + wp + rb);
                ah[1] = *(const u32*)(Ah + wp + rb8);
                ah[2] = *(const u32*)(Ah + wp + rb + 16);
                ah[3] = *(const u32*)(Ah + wp + rb8 + 16);
                #pragma unroll
                for (int nt = 0; nt < 4; nt++) {
                    const int pxb = phf * 32 + nt * 8;           // px tile base
                    const int swzn = ((pxb >> 3) & 7) << 4;
                    const int nb2 = (pxb + gr) * 144 + bplane;
                    u32 bh2[2];
                    bh2[0] = *(const u32*)(Bh + nb2 + (bbyte ^ swzn));
                    bh2[1] = *(const u32*)(Bh + nb2 + ((bbyte + 16) ^ swzn));
                    mma_f16(acc[nt], ah, bh2);
                }
            }
        }
        #pragma unroll
        for (int nt = 0; nt < 4; nt++) {
            acc[nt][0] += bz0;
            acc[nt][1] += bz0;
            acc[nt][2] += bz1;
            acc[nt][3] += bz1;
        }
        __syncthreads();   // xhi reads done

        // ---- store Dhi TRANSPOSED (rows=channel, cols=px); zero sS ----
        {
            char* Dh = smc + br * 18432;
            char* d0 = Dh + (rbase + gr) * 144;
            char* d1 = d0 + 8 * 144;
            #pragma unroll
            for (int nt = 0; nt < 4; nt++) {
                int pxb = (phf * 32 + nt * 8 + 2 * q) * 2;
                *(u32*)(d0 + pxb) = pack_f16x2(acc[nt][0], acc[nt][1]);
                *(u32*)(d1 + pxb) = pack_f16x2(acc[nt][2], acc[nt][3]);
            }
            if (t < 128) sS[t] = 0.f;
        }
        __syncthreads();

        // ---- GEMM2': warp tile px16 x m16 (A via ldmatrix.trans); fused attn ----
        {
            float acc2[2][4];
            #pragma unroll
            for (int j = 0; j < 2; j++)
                #pragma unroll
                for (int i = 0; i < 4; i++) acc2[j][i] = 0.f;

            const char* B2h = smc + W1_OFF;
            #pragma unroll 2
            for (int kt = 0; kt < 8; kt++) {
                u32 ah[4];
                ldsm_x4_trans(ah, dsm_base + (u32)(kt * 16 * 144));
                const int wpB = (kt >> 2) * 9216 + (kt & 3) * 32 + q * 4;
                #pragma unroll
                for (int j = 0; j < 2; j++) {
                    int nb2 = ((mj * 16 + j * 8) + gr) * 144;
                    u32 bh2[2];
                    bh2[0] = *(const u32*)(B2h + wpB + nb2);
                    bh2[1] = *(const u32*)(B2h + wpB + nb2 + 16);
                    mma_f16(acc2[j], ah, bh2);
                }
            }
            float p0 = 0.f, p8 = 0.f;
            #pragma unroll
            for (int j = 0; j < 2; j++) {
                p0 += w2x[j] * fmaxf(acc2[j][0] + b1x[j], 0.f)
                    + w2y[j] * fmaxf(acc2[j][1] + b1y[j], 0.f);
                p8 += w2x[j] * fmaxf(acc2[j][2] + b1x[j], 0.f)
                    + w2y[j] * fmaxf(acc2[j][3] + b1y[j], 0.f);
            }
            p0 += __shfl_xor_sync(0xffffffffu, p0, 1);
            p0 += __shfl_xor_sync(0xffffffffu, p0, 2);
            p8 += __shfl_xor_sync(0xffffffffu, p8, 1);
            p8 += __shfl_xor_sync(0xffffffffu, p8, 2);
            if (q == 0) {
                atomicAdd(&sS[br * 64 + pxt * 16 + gr], p0);
                atomicAdd(&sS[br * 64 + pxt * 16 + gr + 8], p8);
            }
        }
        __syncthreads();   // D reads + sS done

        // ---- sigmoid + TIR stages raw D into sDt ----
        {
            if (t < 128) sA[t] = 1.f / (1.f + __expf(-(sS[t] + bt2v)));
            if (br == 1) {
                float* sDt = (float*)smc;           // [o*65 + px]
                float* d0 = sDt + (rbase + gr) * 65;
                float* d1 = sDt + (rbase + gr + 8) * 65;
                #pragma unroll
                for (int nt = 0; nt < 4; nt++) {
                    int c0 = phf * 32 + nt * 8 + 2 * q;
                    d0[c0]     = acc[nt][0];
                    d0[c0 + 1] = acc[nt][1];
                    d1[c0]     = acc[nt][2];
                    d1[c0 + 1] = acc[nt][3];
                }
            }
        }
        __syncthreads();

        // ---- fuse + store (RGB warps): out = aR*Dr + aT*Dt ----
        if (br == 0) {
            const float* sDt = (const float*)smc;
            const float* d0 = sDt + (rbase + gr) * 65;
            const float* d1 = sDt + (rbase + gr + 8) * 65;
            float* go = out + (size_t)(b * HALF) * NPIX + pix0;
            float* g0 = go + (size_t)(rbase + gr) * NPIX;
            float* g1 = go + (size_t)(rbase + gr + 8) * NPIX;
            #pragma unroll
            for (int nt = 0; nt < 4; nt++) {
                int c0 = phf * 32 + nt * 8 + 2 * q;
                float aR0 = sA[c0], aR1 = sA[c0 + 1];
                float aT0 = sA[64 + c0], aT1 = sA[64 + c0 + 1];
                float2 v0, v1;
                v0.x = aR0 * acc[nt][0] + aT0 * d0[c0];
                v0.y = aR1 * acc[nt][1] + aT1 * d0[c0 + 1];
                v1.x = aR0 * acc[nt][2] + aT0 * d1[c0];
                v1.y = aR1 * acc[nt][3] + aT1 * d1[c0 + 1];
                *(float2*)(g0 + c0) = v0;
                *(float2*)(g1 + c0) = v1;
            }
        }
    }
}

extern "C" void kernel_launch(void* const* d_in, const int* in_sizes, int n_in,
                              void* d_out, int out_size) {
    const float* x    = (const float*)d_in[0];
    const float* Wg   = (const float*)d_in[1];
    const float* bg   = (const float*)d_in[2];
    const float* Wrgb = (const float*)d_in[3];
    const float* brgb = (const float*)d_in[4];
    const float* Wtir = (const float*)d_in[5];
    const float* btir = (const float*)d_in[6];
    const float* Wt1  = (const float*)d_in[7];
    const float* bt1  = (const float*)d_in[8];
    const float* Wt2  = (const float*)d_in[9];
    const float* bt2  = (const float*)d_in[10];
    float* out = (float*)d_out;

    gate_pool<<<BDIM * CDIM, 320>>>(x);

    cudaFuncSetAttribute(moe_expert, cudaFuncAttributeMaxDynamicSharedMemorySize, SMEM_BYTES);
    dim3 grid(18, BDIM);
    moe_expert<<<grid, 1024, SMEM_BYTES>>>(x, Wg, bg, Wrgb, brgb, Wtir, btir,
                                           Wt1, bt1, Wt2, bt2, out);
}

// round 17
// speedup vs baseline: 1.1444x; 1.1444x over previous
#include <cuda_runtime.h>
#include <cstdint>
#include <math.h>

#define E_EXPERTS 5
#define CDIM      256
#define HALF      128
#define QUART     64
#define BDIM      8
#define NPIX      6400
#define PIX       64

typedef uint32_t u32;
typedef uint16_t u16;

__device__ float g_pooled[BDIM * CDIM];

// ---------- fp16 helpers ----------
__device__ __forceinline__ u32 pack_f16x2(float lo, float hi) {
    u32 r; asm("cvt.rn.f16x2.f32 %0, %1, %2;" : "=r"(r) : "f"(hi), "f"(lo)); return r;
}
__device__ __forceinline__ float2 unpack_f16x2(u32 v) {
    float2 f;
    asm("{\n .reg .b16 l,h;\n mov.b32 {l,h}, %2;\n cvt.f32.f16 %0, l;\n cvt.f32.f16 %1, h;\n}"
        : "=f"(f.x), "=f"(f.y) : "r"(v));
    return f;
}

// ---------- warp mma: D(16x8,f32) += A(16x16,f16 row) * B(16x8,f16 col) ----------
__device__ __forceinline__ void mma_f16(float* d, const u32* a, const u32* b) {
    asm volatile("mma.sync.aligned.m16n8k16.row.col.f32.f16.f16.f32 "
        "{%0,%1,%2,%3},{%4,%5,%6,%7},{%8,%9},{%0,%1,%2,%3};"
        : "+f"(d[0]), "+f"(d[1]), "+f"(d[2]), "+f"(d[3])
        : "r"(a[0]), "r"(a[1]), "r"(a[2]), "r"(a[3]), "r"(b[0]), "r"(b[1]));
}

// ---------- ldmatrix x4 transposed (b16) ----------
__device__ __forceinline__ void ldsm_x4_trans(u32* r, u32 saddr) {
    asm volatile("ldmatrix.sync.aligned.m8n8.x4.trans.shared.b16 {%0,%1,%2,%3}, [%4];"
        : "=r"(r[0]), "=r"(r[1]), "=r"(r[2]), "=r"(r[3]) : "r"(saddr));
}

// ======================= gate kernel 1 (pool) =======================
__global__ void __launch_bounds__(320) gate_pool(const float* __restrict__ x) {
    int bc = blockIdx.x;
    const float4* p4 = (const float4*)(x + (size_t)bc * NPIX);
    float s = 0.f;
    #pragma unroll
    for (int k = 0; k < 5; k++) {
        float4 v = __ldg(p4 + k * 320 + threadIdx.x);
        s += (v.x + v.y) + (v.z + v.w);
    }
    __shared__ float red[10];
    #pragma unroll
    for (int o = 16; o; o >>= 1) s += __shfl_down_sync(0xffffffffu, s, o);
    if ((threadIdx.x & 31) == 0) red[threadIdx.x >> 5] = s;
    __syncthreads();
    if (threadIdx.x < 32) {
        float v = (threadIdx.x < 10) ? red[threadIdx.x] : 0.f;
        #pragma unroll
        for (int o = 8; o; o >>= 1) v += __shfl_down_sync(0xffffffffu, v, o);
        if (threadIdx.x == 0) g_pooled[bc] = v * (1.0f / (float)NPIX);
    }
}

// ======================= smem layout (bytes) =======================
// xhi: DOUBLE buffered, swizzled split-row fp16 (per buf: 2 br x 2 planes x
//      64 px-rows x 144B); byte' = byte ^ ((px>>3 & 7) << 4)
// Dhi: DEDICATED, transposed (per br: 128 channel-rows x 144B), fp16;
//      GEMM2 A via ldmatrix.trans; fuse reads TIR half directly (fp16).
// W  : W' = W + I  (per br: 2 planes x 128 rows x 144B)
// W1 : 2 planes x 64 rows x 144B
#define XHI0_OFF 0
#define XHI1_OFF 36864
#define DHI_OFF  73728
#define W_OFF    110592
#define W1_OFF   184320
#define SA_OFF   202752
#define SS_OFF   203264
#define SMEM_BYTES 203776

__global__ void __launch_bounds__(512, 1) moe_expert(
    const float* __restrict__ x,
    const float* __restrict__ Wg,   const float* __restrict__ bg,
    const float* __restrict__ Wrgb, const float* __restrict__ brgb,
    const float* __restrict__ Wtir, const float* __restrict__ btir,
    const float* __restrict__ Wt1,  const float* __restrict__ bt1,
    const float* __restrict__ Wt2,  const float* __restrict__ bt2,
    float* __restrict__ out)
{
    extern __shared__ char smc[];
    float* sA = (float*)(smc + SA_OFF);
    float* sS = (float*)(smc + SS_OFF);

    const int t    = threadIdx.x;
    const int w    = t >> 5;
    const int lane = t & 31;
    const int gr   = lane >> 2;
    const int q    = lane & 3;
    const int br   = w >> 3;            // branch: 0=RGB, 1=TIR
    const int msub = w & 7;
    const int rbase = msub * 16;        // GEMM1 o-rows

    const int b = blockIdx.y;

    // ---- inline gate: warp e computes logit e; argmax (strict >, first max) ----
    if (w < E_EXPERTS) {
        const float* pw = Wg + w * CDIM;
        const float* pp = g_pooled + b * CDIM;
        float s = 0.f;
        #pragma unroll
        for (int c = lane; c < CDIM; c += 32) s += pp[c] * pw[c];
        #pragma unroll
        for (int o = 16; o; o >>= 1) s += __shfl_down_sync(0xffffffffu, s, o);
        if (lane == 0) sS[w] = s + __ldg(bg + w);
    }
    __syncthreads();
    int e = 0;
    {
        float best = sS[0];
        #pragma unroll
        for (int i = 1; i < E_EXPERTS; i++) {
            float v = sS[i];
            if (v > best) { best = v; e = i; }
        }
    }

    // 18 blocks/batch: 10x6 + 8x5 = 100 tiles of 64 px (144 blocks = 1 wave)
    const int ib    = blockIdx.x;
    const int tile0 = ib < 10 ? ib * 6 : 60 + (ib - 10) * 5;
    const int tcnt  = ib < 10 ? 6 : 5;

    // ---- hoisted per-thread constants ----
    const float bz0 = __ldg((br ? btir : brgb) + e * HALF + rbase + gr);
    const float bz1 = __ldg((br ? btir : brgb) + e * HALF + rbase + gr + 8);
    const int   pxt   = msub >> 1;      // GEMM2 px 16-tile (0..3)
    const int   npair = msub & 1;       // GEMM2 m-half
    float w2x[4], w2y[4], b1x[4], b1y[4];
    #pragma unroll
    for (int j = 0; j < 4; j++) {
        int m0 = (npair * 4 + j) * 8 + 2 * q;
        w2x[j] = __ldg(Wt2 + e * QUART + m0);
        w2y[j] = __ldg(Wt2 + e * QUART + m0 + 1);
        b1x[j] = __ldg(bt1 + e * QUART + m0);
        b1y[j] = __ldg(bt1 + e * QUART + m0 + 1);
    }
    const float bt2v = __ldg(bt2 + e);

    // ------------ prologue: W' = W + I, W1 -> fp16 in smem ------------
    #pragma unroll
    for (int br2 = 0; br2 < 2; br2++) {
        const float* gW = (br2 ? Wtir : Wrgb) + (size_t)e * HALF * HALF;
        char* bh = smc + W_OFF + br2 * 36864;
        #pragma unroll 4
        for (int it = 0; it < 16; it++) {
            int lin = it * 512 + t;            // 8192 = 128 o x 64 c-pairs
            int o = lin >> 6, c0 = (lin & 63) * 2;
            float2 v = __ldg((const float2*)(gW + o * 128 + c0));
            float vx = v.x + ((o == c0)     ? 1.f : 0.f);   // residual fold
            float vy = v.y + ((o == c0 + 1) ? 1.f : 0.f);
            int addr = (c0 >> 6) * 18432 + o * 144 + (c0 & 63) * 2;
            *(u32*)(bh + addr) = pack_f16x2(vx, vy);
        }
    }
    {
        const float* g1 = Wt1 + (size_t)e * QUART * HALF;
        char* bh = smc + W1_OFF;
        #pragma unroll 4
        for (int it = 0; it < 8; it++) {
            int lin = it * 512 + t;            // 4096 = 64 m x 64 c-pairs
            int m = lin >> 6, c0 = (lin & 63) * 2;
            float2 v = __ldg((const float2*)(g1 + m * 128 + c0));
            int addr = (c0 >> 6) * 9216 + m * 144 + (c0 & 63) * 2;
            *(u32*)(bh + addr) = pack_f16x2(v.x, v.y);
        }
    }

    // ---- Bx builder mapping: 2 channel-pairs per thread (cp8, cp8+64) ----
    const int cp8 = t >> 3;                       // 0..63
    const int sub = t & 7;
    int  bb_off[2], cinv[2];
    const float* gxp[2];
    #pragma unroll
    for (int it = 0; it < 2; it++) {
        int c0b = 2 * (cp8 + it * 64);
        bb_off[it] = (c0b >> 7) * 18432 + ((c0b & 64) ? 9216 : 0);
        cinv[it]   = (c0b & 63) * 2;
        gxp[it]    = x + ((size_t)(b * CDIM + c0b)) * NPIX;
    }

    // ---- GEMM2 A ldmatrix lane base (transposed Dhi, dedicated) ----
    const int l2   = lane & 7;
    const int tl   = lane >> 3;
    const int arow = l2 + ((tl & 2) ? 8 : 0);
    const int acol = pxt * 32 + ((tl & 1) ? 16 : 0);
    const u32 dsm_base = (u32)__cvta_generic_to_shared(smc + DHI_OFF + br * 18432)
                       + (u32)(arow * 144 + acol);

    // ---- initial build: tile0 -> xhi buf 0 (both channel-pair groups) ----
    #pragma unroll
    for (int it = 0; it < 2; it++) {
        char* bb = smc + XHI0_OFF + bb_off[it];
        const float* g0 = gxp[it] + tile0 * PIX;
        #pragma unroll
        for (int j = 0; j < 2; j++) {
            float4 a0 = __ldg((const float4*)(g0 + sub * 4 + j * 32));
            float4 a1 = __ldg((const float4*)(g0 + NPIX + sub * 4 + j * 32));
            int px0 = sub * 4 + j * 32;
            int cinx = cinv[it] ^ ((((px0 >> 3) & 7) << 4));
            *(u32*)(bb + (px0    ) * 144 + cinx) = pack_f16x2(a0.x, a1.x);
            *(u32*)(bb + (px0 + 1) * 144 + cinx) = pack_f16x2(a0.y, a1.y);
            *(u32*)(bb + (px0 + 2) * 144 + cinx) = pack_f16x2(a0.z, a1.z);
            *(u32*)(bb + (px0 + 3) * 144 + cinx) = pack_f16x2(a0.w, a1.w);
        }
    }

    for (int tt = 0; tt < tcnt; tt++) {
        const int pix0 = (tile0 + tt) * PIX;
        const int cur  = (tt & 1) ? XHI1_OFF : XHI0_OFF;
        const int nxt  = (tt & 1) ? XHI0_OFF : XHI1_OFF;
        __syncthreads();   // B1: xhi[cur] ready; prev fuse done (Dhi free)

        // ---- GEMM1: acc[8][4] = W'hi@xhi over N=64 (residual inside W') ----
        float acc[8][4];
        #pragma unroll
        for (int nt = 0; nt < 8; nt++)
            #pragma unroll
            for (int i = 0; i < 4; i++) acc[nt][i] = 0.f;
        {
            const char* Ah = smc + W_OFF + br * 36864;
            const char* Bh = smc + cur + br * 18432;
            const int rb = (rbase + gr) * 144, rb8 = rb + 1152;
            #pragma unroll 2
            for (int kt = 0; kt < 8; kt++) {
                const int wp = (kt >> 2) * 18432 + (kt & 3) * 32 + q * 4;
                const int bplane = (kt >> 2) * 9216;
                const int bbyte  = (kt & 3) * 32 + q * 4;
                u32 ah[4];
                ah[0] = *(const u32*)(Ah + wp + rb);
                ah[1] = *(const u32*)(Ah + wp + rb8);
                ah[2] = *(const u32*)(Ah + wp + rb + 16);
                ah[3] = *(const u32*)(Ah + wp + rb8 + 16);
                #pragma unroll
                for (int nt = 0; nt < 8; nt++) {
                    const int swzn = (nt & 7) << 4;
                    const int nb2 = (nt * 8 + gr) * 144 + bplane;
                    u32 bh2[2];
                    bh2[0] = *(const u32*)(Bh + nb2 + (bbyte ^ swzn));
                    bh2[1] = *(const u32*)(Bh + nb2 + ((bbyte + 16) ^ swzn));
                    mma_f16(acc[nt], ah, bh2);
                }
            }
        }
        #pragma unroll
        for (int nt = 0; nt < 8; nt++) {
            acc[nt][0] += bz0;
            acc[nt][1] += bz0;
            acc[nt][2] += bz1;
            acc[nt][3] += bz1;
        }

        // ---- phase B: builder LDGs first, Dhi store, builder STS, zero sS ----
        {
            const bool more = (tt + 1 < tcnt);
            float4 a0[2][2], a1[2][2];
            if (more) {
                #pragma unroll
                for (int it = 0; it < 2; it++) {
                    const float* g0 = gxp[it] + pix0 + PIX;
                    #pragma unroll
                    for (int j = 0; j < 2; j++) {
                        a0[it][j] = __ldg((const float4*)(g0 + sub * 4 + j * 32));
                        a1[it][j] = __ldg((const float4*)(g0 + NPIX + sub * 4 + j * 32));
                    }
                }
            }
            char* Dh = smc + DHI_OFF + br * 18432;
            char* d0 = Dh + (rbase + gr) * 144;
            char* d1 = d0 + 8 * 144;
            #pragma unroll
            for (int nt = 0; nt < 8; nt++) {
                int pxb = (nt * 8 + 2 * q) * 2;
                *(u32*)(d0 + pxb) = pack_f16x2(acc[nt][0], acc[nt][1]);
                *(u32*)(d1 + pxb) = pack_f16x2(acc[nt][2], acc[nt][3]);
            }
            if (t < 128) sS[t] = 0.f;
            if (more) {
                #pragma unroll
                for (int it = 0; it < 2; it++) {
                    char* bb = smc + nxt + bb_off[it];
                    #pragma unroll
                    for (int j = 0; j < 2; j++) {
                        int px0 = sub * 4 + j * 32;
                        int cinx = cinv[it] ^ ((((px0 >> 3) & 7) << 4));
                        *(u32*)(bb + (px0    ) * 144 + cinx) = pack_f16x2(a0[it][j].x, a1[it][j].x);
                        *(u32*)(bb + (px0 + 1) * 144 + cinx) = pack_f16x2(a0[it][j].y, a1[it][j].y);
                        *(u32*)(bb + (px0 + 2) * 144 + cinx) = pack_f16x2(a0[it][j].z, a1[it][j].z);
                        *(u32*)(bb + (px0 + 3) * 144 + cinx) = pack_f16x2(a0[it][j].w, a1[it][j].w);
                    }
                }
            }
        }
        __syncthreads();   // B2: Dhi + sS-zero (+ xhi[nxt]) visible

        // ---- GEMM2': h^T = Dhi@W1hi^T (A via ldmatrix.trans); fused attention ----
        {
            float acc2[4][4];
            #pragma unroll
            for (int j = 0; j < 4; j++)
                #pragma unroll
                for (int i = 0; i < 4; i++) acc2[j][i] = 0.f;

            const char* B2h = smc + W1_OFF;
            #pragma unroll 2
            for (int kt = 0; kt < 8; kt++) {
                u32 ah[4];
                ldsm_x4_trans(ah, dsm_base + (u32)(kt * 16 * 144));
                const int wpB = (kt >> 2) * 9216 + (kt & 3) * 32 + q * 4;
                #pragma unroll
                for (int j = 0; j < 4; j++) {
                    int nb2 = ((npair * 4 + j) * 8 + gr) * 144;
                    u32 bh2[2];
                    bh2[0] = *(const u32*)(B2h + wpB + nb2);
                    bh2[1] = *(const u32*)(B2h + wpB + nb2 + 16);
                    mma_f16(acc2[j], ah, bh2);
                }
            }
            float p0 = 0.f, p8 = 0.f;
            #pragma unroll
            for (int j = 0; j < 4; j++) {
                p0 += w2x[j] * fmaxf(acc2[j][0] + b1x[j], 0.f)
                    + w2y[j] * fmaxf(acc2[j][1] + b1y[j], 0.f);
                p8 += w2x[j] * fmaxf(acc2[j][2] + b1x[j], 0.f)
                    + w2y[j] * fmaxf(acc2[j][3] + b1y[j], 0.f);
            }
            p0 += __shfl_xor_sync(0xffffffffu, p0, 1);
            p0 += __shfl_xor_sync(0xffffffffu, p0, 2);
            p8 += __shfl_xor_sync(0xffffffffu, p8, 1);
            p8 += __shfl_xor_sync(0xffffffffu, p8, 2);
            if (q == 0) {
                atomicAdd(&sS[br * 64 + pxt * 16 + gr], p0);
                atomicAdd(&sS[br * 64 + pxt * 16 + gr + 8], p8);
            }
        }
        __syncthreads();   // B3: sS complete

        // ---- sigmoid ----
        if (t < 128) sA[t] = 1.f / (1.f + __expf(-(sS[t] + bt2v)));
        __syncthreads();   // B4: sA ready

        // ---- fuse + store (RGB warps): out = aR*Dr(acc) + aT*Dt(fp16 smem) ----
        if (br == 0) {
            const char* Dt = smc + DHI_OFF + 18432;     // TIR Dhi, transposed
            const char* dt0 = Dt + (rbase + gr) * 144;
            const char* dt1 = dt0 + 8 * 144;
            float* go = out + (size_t)(b * HALF) * NPIX + pix0;
            float* g0 = go + (size_t)(rbase + gr) * NPIX;
            float* g1 = go + (size_t)(rbase + gr + 8) * NPIX;
            #pragma unroll
            for (int nt = 0; nt < 8; nt++) {
                int c0 = nt * 8 + 2 * q;
                float aR0 = sA[c0], aR1 = sA[c0 + 1];
                float aT0 = sA[64 + c0], aT1 = sA[64 + c0 + 1];
                float2 t0 = unpack_f16x2(*(const u32*)(dt0 + c0 * 2));
                float2 t1 = unpack_f16x2(*(const u32*)(dt1 + c0 * 2));
                float2 v0, v1;
                v0.x = aR0 * acc[nt][0] + aT0 * t0.x;
                v0.y = aR1 * acc[nt][1] + aT1 * t0.y;
                v1.x = aR0 * acc[nt][2] + aT0 * t1.x;
                v1.y = aR1 * acc[nt][3] + aT1 * t1.y;
                *(float2*)(g0 + c0) = v0;
                *(float2*)(g1 + c0) = v1;
            }
        }
        // loop-top B1 protects Dhi reuse (fuse reads done) + xhi[next] visibility
    }
}

extern "C" void kernel_launch(void* const* d_in, const int* in_sizes, int n_in,
                              void* d_out, int out_size) {
    const float* x    = (const float*)d_in[0];
    const float* Wg   = (const float*)d_in[1];
    const float* bg   = (const float*)d_in[2];
    const float* Wrgb = (const float*)d_in[3];
    const float* brgb = (const float*)d_in[4];
    const float* Wtir = (const float*)d_in[5];
    const float* btir = (const float*)d_in[6];
    const float* Wt1  = (const float*)d_in[7];
    const float* bt1  = (const float*)d_in[8];
    const float* Wt2  = (const float*)d_in[9];
    const float* bt2  = (const float*)d_in[10];
    float* out = (float*)d_out;

    gate_pool<<<BDIM * CDIM, 320>>>(x);

    cudaFuncSetAttribute(moe_expert, cudaFuncAttributeMaxDynamicSharedMemorySize, SMEM_BYTES);
    dim3 grid(18, BDIM);
    moe_expert<<<grid, 512, SMEM_BYTES>>>(x, Wg, bg, Wrgb, brgb, Wtir, btir,
                                          Wt1, bt1, Wt2, bt2, out);
}